// round 5
// baseline (speedup 1.0000x reference)
#include <cuda_runtime.h>

#define S        2048   // NUM_SLICE
#define INCH     2048
#define H        100
#define G4       400    // 4*H gate rows
#define ITERLIM  128

// scratch for x_gates [S][G4] (accumulated via atomics; zeroed by init kernel)
__device__ float g_xg[S * G4];
// per-s-tile completion counters (32 tiles of 64 slices; ready at 14 blocks)
__device__ int g_cnt[32];

// ---------------- f32x2 packed-FMA helpers (Blackwell) ----------------
__device__ __forceinline__ unsigned long long pk2(float lo, float hi) {
    unsigned long long r;
    asm("mov.b64 %0, {%1,%2};" : "=l"(r) : "f"(lo), "f"(hi));
    return r;
}
__device__ __forceinline__ float2 upk2(unsigned long long v) {
    float2 f;
    asm("mov.b64 {%0,%1}, %2;" : "=f"(f.x), "=f"(f.y) : "l"(v));
    return f;
}
__device__ __forceinline__ unsigned long long ffma2(unsigned long long a,
                                                    unsigned long long b,
                                                    unsigned long long c) {
    unsigned long long d;
    asm("fma.rn.f32x2 %0, %1, %2, %3;" : "=l"(d) : "l"(a), "l"(b), "l"(c));
    return d;
}

// ---------------- activations (__expf ~2 ulp) ----------------
__device__ __forceinline__ float sigf(float x) {
    return __fdividef(1.0f, 1.0f + __expf(-x));
}
__device__ __forceinline__ float tanhf_(float x) {
    return __fdividef(2.0f, 1.0f + __expf(-2.0f * x)) - 1.0f;
}

// =====================================================================
// init: zero g_xg and g_cnt
// =====================================================================
__global__ void zero_scratch() {
    int i = blockIdx.x * 1024 + threadIdx.x;
    if (i < S * G4) g_xg[i] = 0.0f;
    if (i < 32) g_cnt[i] = 0;
}

// =====================================================================
// Fused kernel.
//   block 0          : persistent LSTM scan (phase 1 + phase 2)
//   blocks 1..448    : GEMM x_gates, 64s x 64r tiles, k split in halves.
//     unit u = bid-1 : kh = u&1, v = u>>1, st = v/7 (s-tile), rt = v%7.
//     s-tile-major ordering => earliest tiles finish first.
//     Each block atomicAdds its partial (+bias for kh==0) into g_xg,
//     then bumps g_cnt[st]. Tile ready when g_cnt[st]==14.
// =====================================================================
#define BM 64
#define BN 64
#define BK 16
#define KH 1024         // k-half length
#define RDY 14          // blocks per s-tile

// ---- scan step macro ----
// h layout per buffer: h[0..49] at +0, h[50..99] at +64 (both 16B aligned).
#define LSTM_STEP(XGA, XGB)                                                       \
    {                                                                             \
        const float4* hv4 = (const float4*)(hsf + buf * 128 + p * 64);            \
        unsigned long long ac0 = 0ull, ac1 = 0ull, ac2 = 0ull, ac3 = 0ull;        \
        _Pragma("unroll")                                                         \
        for (int j = 0; j < 12; j++) {                                            \
            float4 q = hv4[j];                                                    \
            unsigned long long lo = pk2(q.x, q.y);                                \
            unsigned long long hi = pk2(q.z, q.w);                                \
            ac0 = ffma2(w0[2 * j], lo, ac0);                                      \
            ac1 = ffma2(w1[2 * j], lo, ac1);                                      \
            ac2 = ffma2(w2[2 * j], lo, ac2);                                      \
            ac3 = ffma2(w3[2 * j], lo, ac3);                                      \
            ac0 = ffma2(w0[2 * j + 1], hi, ac0);                                  \
            ac1 = ffma2(w1[2 * j + 1], hi, ac1);                                  \
            ac2 = ffma2(w2[2 * j + 1], hi, ac2);                                  \
            ac3 = ffma2(w3[2 * j + 1], hi, ac3);                                  \
        }                                                                         \
        {                                                                         \
            unsigned long long last = ((const unsigned long long*)hv4)[24];       \
            ac0 = ffma2(w0[24], last, ac0);                                       \
            ac1 = ffma2(w1[24], last, ac1);                                       \
            ac2 = ffma2(w2[24], last, ac2);                                       \
            ac3 = ffma2(w3[24], last, ac3);                                       \
        }                                                                         \
        float2 f0 = upk2(ac0), f1 = upk2(ac1), f2 = upk2(ac2), f3 = upk2(ac3);    \
        float z0 = f0.x + f0.y;                                                   \
        float z1 = f1.x + f1.y;                                                   \
        float z2 = f2.x + f2.y;                                                   \
        float z3 = f3.x + f3.y;                                                   \
        float zA = p ? z1 : z0;                                                   \
        float zB = p ? z3 : z2;                                                   \
        float sA = p ? z0 : z1;                                                   \
        float sB = p ? z2 : z3;                                                   \
        zA += __shfl_xor_sync(0xffffffffu, sA, 1);                                \
        zB += __shfl_xor_sync(0xffffffffu, sB, 1);                                \
        zA += (XGA);                                                              \
        zB += (XGB);                                                              \
        /* lane0: nlA=sig(i), nlB=tanh(g); lane1: nlA=sig(f), nlB=sig(o) */       \
        float nlA = sigf(zA);                                                     \
        float aB  = p ? -zB : -(zB + zB);                                         \
        float eB  = __expf(aB);                                                   \
        float sB2 = __fdividef(1.0f, 1.0f + eB);                                  \
        float nlB = p ? sB2 : (sB2 + sB2 - 1.0f);                                 \
        float gA = __shfl_xor_sync(0xffffffffu, nlA, 1);                          \
        float gB = __shfl_xor_sync(0xffffffffu, nlB, 1);                          \
        if (p == 0 && act) {                                                      \
            float cn = gA * creg + nlA * nlB;                                     \
            creg = cn;                                                            \
            float hn = gB * tanhf_(cn);                                           \
            hsf[(buf ^ 1) * 128 + ((rg < 50) ? rg : (64 + rg - 50))] = hn;        \
        }                                                                         \
        __syncthreads();                                                          \
        buf ^= 1;                                                                 \
    }

// uniform-branch tile gate (poll per-tile counters, then block-wide barrier)
#define ENSURE(TL)                                                                \
    if ((TL) > readyTile) {                                                       \
        if (tid == 0) {                                                           \
            for (int z_ = readyTile + 1; z_ <= (TL); z_++)                        \
                while (((volatile int*)g_cnt)[z_] < RDY) {}                       \
        }                                                                         \
        __syncthreads();                                                          \
        readyTile = (TL);                                                         \
    }

__global__ __launch_bounds__(256, 1) void fused(const float* __restrict__ x,
                                                const float* __restrict__ Wih,
                                                const float* __restrict__ Whh,
                                                const float* __restrict__ bih,
                                                const float* __restrict__ bhh,
                                                const float* __restrict__ Wfc,
                                                const float* __restrict__ bfc,
                                                float* __restrict__ out) {
    const int tid = threadIdx.x;

    // All shared memory at function scope with explicit 16B alignment —
    // the R4 fault was a float4 LDS on a 4-byte-aligned scoped array.
    __shared__ __align__(16) float xs[BK][BM];
    __shared__ __align__(16) float ws[BN][BK];
    __shared__ __align__(16) float hsf[2 * 128];
    __shared__ __align__(16) float swfc[3 * H];
    __shared__ float sbfc[3];
    __shared__ int s_idx;
    __shared__ int s_done;

    if (blockIdx.x != 0) {
        // ===================== GEMM path =====================
        const int u = blockIdx.x - 1;
        const int kh = u & 1;
        const int v = u >> 1;
        const int st = v / 7;
        const int rt = v - st * 7;
        const int s0 = st * BM;
        const int r0 = rt * BN;
        const int kbase = kh * KH;

        const int tx = tid & 15;
        const int ty = tid >> 4;

        unsigned long long a0[4], a1[4];
#pragma unroll
        for (int j = 0; j < 4; j++) { a0[j] = 0ull; a1[j] = 0ull; }

        for (int kt = 0; kt < KH; kt += BK) {
            const int k0 = kbase + kt;
#pragma unroll
            for (int i = 0; i < 4; i++) {
                int idx = tid + i * 256;
                int kk = idx >> 6, si = idx & 63;
                xs[kk][si] = x[(k0 + kk) * S + s0 + si];
            }
#pragma unroll
            for (int i = 0; i < 4; i++) {
                int idx = tid + i * 256;
                int kk = idx & 15, rj = idx >> 4;
                int r = r0 + rj;
                ws[rj][kk] = (r < G4) ? Wih[r * INCH + k0 + kk] : 0.0f;
            }
            __syncthreads();

#pragma unroll
            for (int kk = 0; kk < BK; kk++) {
                float4 xv = *(const float4*)&xs[kk][tx * 4];
                unsigned long long xlo = pk2(xv.x, xv.y);
                unsigned long long xhi = pk2(xv.z, xv.w);
#pragma unroll
                for (int jj = 0; jj < 4; jj++) {
                    float wv = ws[ty * 4 + jj][kk];
                    unsigned long long wd = pk2(wv, wv);
                    a0[jj] = ffma2(xlo, wd, a0[jj]);
                    a1[jj] = ffma2(xhi, wd, a1[jj]);
                }
            }
            __syncthreads();
        }

#pragma unroll
        for (int jj = 0; jj < 4; jj++) {
            int r = r0 + ty * 4 + jj;
            if (r < G4) {
                float bb = (kh == 0) ? (bih[r] + bhh[r]) : 0.0f;
                float2 v0 = upk2(a0[jj]);
                float2 v1 = upk2(a1[jj]);
                int sb = s0 + tx * 4;
                atomicAdd(&g_xg[(sb + 0) * G4 + r], v0.x + bb);
                atomicAdd(&g_xg[(sb + 1) * G4 + r], v0.y + bb);
                atomicAdd(&g_xg[(sb + 2) * G4 + r], v1.x + bb);
                atomicAdd(&g_xg[(sb + 3) * G4 + r], v1.y + bb);
            }
        }
        __threadfence();
        __syncthreads();
        if (tid == 0) atomicAdd(&g_cnt[st], 1);
        return;
    }

    // ===================== scan path (block 0) =====================
    const int rg = tid >> 1;   // 0..127 (active < 100)
    const int p = tid & 1;     // k-half
    const bool act = (rg < H);

    const int rA = p * H + rg;         // gate p row
    const int rB = (p + 2) * H + rg;   // gate p+2 row

    for (int i = tid; i < 2 * 128; i += 256) hsf[i] = 0.0f;
    for (int i = tid; i < 3 * H; i += 256) swfc[i] = Wfc[i];
    if (tid < 3) sbfc[tid] = bfc[tid];
    if (tid == 0) { s_idx = S / 2; s_done = 0; }

    // W_hh rows into registers: 4 gates x 25 f32x2, k in [50p, 50p+50)
    unsigned long long w0[25], w1[25], w2[25], w3[25];
    {
        const int r0 = rg, r1 = rg + H, r2 = rg + 2 * H, r3 = rg + 3 * H;
#pragma unroll
        for (int j = 0; j < 25; j++) {
            int k0 = 50 * p + 2 * j;
            float a0 = 0, b0 = 0, a1 = 0, b1 = 0, a2 = 0, b2 = 0, a3 = 0, b3 = 0;
            if (act) {
                a0 = Whh[r0 * H + k0]; b0 = Whh[r0 * H + k0 + 1];
                a1 = Whh[r1 * H + k0]; b1 = Whh[r1 * H + k0 + 1];
                a2 = Whh[r2 * H + k0]; b2 = Whh[r2 * H + k0 + 1];
                a3 = Whh[r3 * H + k0]; b3 = Whh[r3 * H + k0 + 1];
            }
            w0[j] = pk2(a0, b0);
            w1[j] = pk2(a1, b1);
            w2[j] = pk2(a2, b2);
            w3[j] = pk2(a3, b3);
        }
    }
    float creg = 0.0f;
    int readyTile = -1;

    __syncthreads();

    int buf = 0;

    // ---------------- phase 1 ----------------
    ENSURE(0)
    float xgA = act ? g_xg[rA] : 0.0f;
    float xgB = act ? g_xg[rB] : 0.0f;
#pragma unroll 1
    for (int t = 0; t < S; t++) {
        float xgA_n = 0.0f, xgB_n = 0.0f;
        if (t + 1 < S) {
            ENSURE((t + 1) >> 6)
            if (act) {
                xgA_n = g_xg[(t + 1) * G4 + rA];
                xgB_n = g_xg[(t + 1) * G4 + rB];
            }
        }
        LSTM_STEP(xgA, xgB)
        xgA = xgA_n;
        xgB = xgB_n;
    }

    // all tiles ready before random-access phase 2
    ENSURE(31)

    // ---------------- phase 2 ----------------
    float o0 = 0.0f, o1 = 0.0f;
    int consec = 0;

    int t = S / 2;
    xgA = act ? g_xg[t * G4 + rA] : 0.0f;
    xgB = act ? g_xg[t * G4 + rB] : 0.0f;

#pragma unroll 1
    for (int it = 0; it < ITERLIM; it++) {
        const int tp = (t + 1) & (S - 1);
        const int tm = (t - 1) & (S - 1);
        float pA = 0, pB = 0, mA = 0, mB = 0;
        if (act) {
            pA = g_xg[tp * G4 + rA];
            pB = g_xg[tp * G4 + rB];
            mA = g_xg[tm * G4 + rA];
            mB = g_xg[tm * G4 + rB];
        }

        LSTM_STEP(xgA, xgB)

        if (tid < 32) {
            float q0 = 0.0f, q1 = 0.0f, q2 = 0.0f;
            for (int k = tid; k < H; k += 32) {
                float h = hsf[buf * 128 + ((k < 50) ? k : (64 + k - 50))];
                q0 += swfc[k] * h;
                q1 += swfc[H + k] * h;
                q2 += swfc[2 * H + k] * h;
            }
#pragma unroll
            for (int off = 16; off; off >>= 1) {
                q0 += __shfl_down_sync(0xffffffffu, q0, off);
                q1 += __shfl_down_sync(0xffffffffu, q1, off);
                q2 += __shfl_down_sync(0xffffffffu, q2, off);
            }
            if (tid == 0) {
                q0 += sbfc[0]; q1 += sbfc[1]; q2 += sbfc[2];
                o0 = q0;
                o1 = q1;
                consec = (q1 > 0.0f) ? (consec + 1) : 0;
                if (consec > 3) s_done = 1;
                s_idx = (q2 > 0.0f) ? tp : tm;
            }
        }
        __syncthreads();
        if (s_done) break;
        const int tn = s_idx;
        const bool fwd = (tn == tp);
        xgA = fwd ? pA : mA;
        xgB = fwd ? pB : mB;
        t = tn;
    }

    if (tid == 0) {
        out[0] = o0;
        out[1] = o1;
    }
}

// =====================================================================
// launch
// =====================================================================
extern "C" void kernel_launch(void* const* d_in, const int* in_sizes, int n_in,
                              void* d_out, int out_size) {
    const float* x   = (const float*)d_in[0];
    const float* Wih = (const float*)d_in[1];
    const float* Whh = (const float*)d_in[2];
    const float* bih = (const float*)d_in[3];
    const float* bhh = (const float*)d_in[4];
    const float* Wfc = (const float*)d_in[5];
    const float* bfc = (const float*)d_in[6];
    float* out = (float*)d_out;

    zero_scratch<<<(S * G4 + 1023) / 1024, 1024>>>();
    fused<<<1 + 448, 256>>>(x, Wih, Whh, bih, bhh, Wfc, bfc, out);
}

// round 6
// speedup vs baseline: 1.0744x; 1.0744x over previous
#include <cuda_runtime.h>

#define S        2048   // NUM_SLICE
#define INCH     2048
#define H        100
#define G4       400    // 4*H gate rows
#define ITERLIM  128

// scratch for x_gates [S][G4] (includes b_ih + b_hh)
__device__ float g_xg[S * G4];

// ---------------- f32x2 packed-FMA helpers (Blackwell) ----------------
__device__ __forceinline__ unsigned long long pk2(float lo, float hi) {
    unsigned long long r;
    asm("mov.b64 %0, {%1,%2};" : "=l"(r) : "f"(lo), "f"(hi));
    return r;
}
__device__ __forceinline__ float2 upk2(unsigned long long v) {
    float2 f;
    asm("mov.b64 {%0,%1}, %2;" : "=f"(f.x), "=f"(f.y) : "l"(v));
    return f;
}
__device__ __forceinline__ unsigned long long ffma2(unsigned long long a,
                                                    unsigned long long b,
                                                    unsigned long long c) {
    unsigned long long d;
    asm("fma.rn.f32x2 %0, %1, %2, %3;" : "=l"(d) : "l"(a), "l"(b), "l"(c));
    return d;
}

// ---------------- hardware tanh (MUFU.TANH, sm_75+) ----------------
__device__ __forceinline__ float tanhapx(float x) {
    float y;
    asm("tanh.approx.f32 %0, %1;" : "=f"(y) : "f"(x));
    return y;
}

// =====================================================================
// Kernel 1: x_gates[s][r] = sum_k x[k*S+s] * Wih[r*INCH+k] + bih[r] + bhh[r]
// =====================================================================
#define BM 64
#define BN 64
#define BK 16

__global__ __launch_bounds__(256) void gemm_xgates(const float* __restrict__ x,
                                                   const float* __restrict__ Wih,
                                                   const float* __restrict__ bih,
                                                   const float* __restrict__ bhh) {
    __shared__ __align__(16) float xs[BK][BM];
    __shared__ __align__(16) float ws[BN][BK];

    const int tid = threadIdx.x;
    const int s0 = blockIdx.x * BM;
    const int r0 = blockIdx.y * BN;
    const int tx = tid & 15;
    const int ty = tid >> 4;

    unsigned long long a0[4], a1[4];
#pragma unroll
    for (int j = 0; j < 4; j++) { a0[j] = 0ull; a1[j] = 0ull; }

    for (int k0 = 0; k0 < INCH; k0 += BK) {
#pragma unroll
        for (int i = 0; i < 4; i++) {
            int idx = tid + i * 256;
            int kk = idx >> 6, si = idx & 63;
            xs[kk][si] = x[(k0 + kk) * S + s0 + si];
        }
#pragma unroll
        for (int i = 0; i < 4; i++) {
            int idx = tid + i * 256;
            int kk = idx & 15, rj = idx >> 4;
            int r = r0 + rj;
            ws[rj][kk] = (r < G4) ? Wih[r * INCH + k0 + kk] : 0.0f;
        }
        __syncthreads();

#pragma unroll
        for (int kk = 0; kk < BK; kk++) {
            float4 xv = *(const float4*)&xs[kk][tx * 4];
            unsigned long long xlo = pk2(xv.x, xv.y);
            unsigned long long xhi = pk2(xv.z, xv.w);
#pragma unroll
            for (int jj = 0; jj < 4; jj++) {
                float wv = ws[ty * 4 + jj][kk];
                unsigned long long wd = pk2(wv, wv);
                a0[jj] = ffma2(xlo, wd, a0[jj]);
                a1[jj] = ffma2(xhi, wd, a1[jj]);
            }
        }
        __syncthreads();
    }

#pragma unroll
    for (int jj = 0; jj < 4; jj++) {
        int r = r0 + ty * 4 + jj;
        if (r < G4) {
            float bb = bih[r] + bhh[r];
            float2 v0 = upk2(a0[jj]);
            float2 v1 = upk2(a1[jj]);
            int sb = s0 + tx * 4;
            g_xg[(sb + 0) * G4 + r] = v0.x + bb;
            g_xg[(sb + 1) * G4 + r] = v0.y + bb;
            g_xg[(sb + 2) * G4 + r] = v1.x + bb;
            g_xg[(sb + 3) * G4 + r] = v1.y + bb;
        }
    }
}

// =====================================================================
// Kernel 2: persistent single-CTA LSTM scan.
// 256 threads: rg = tid>>1 in [0,128) (active < 100), p = tid&1 (k-half).
// Thread (rg,p) holds W_hh rows {rg, rg+H, rg+2H, rg+3H} for k in
// [50p, 50p+50) as 25 packed f32x2 regs per gate (200 weight regs).
// x_gates (incl. biases) folded into accumulator init on the p==0 lane.
// One 4-shfl exchange gives every lane all four full gate sums; both
// lanes redundantly (bit-identically) compute the cell update.
// =====================================================================

// XGI..XGO must be 0 on p==1 lanes and on inactive rows.
#define LSTM_STEP(XGI, XGF, XGG, XGO)                                             \
    {                                                                             \
        const unsigned long long* hc =                                            \
            (const unsigned long long*)&hsf[buf][0] + 25 * p;                     \
        unsigned long long ac0 = pk2((XGI), 0.0f);                                \
        unsigned long long ac1 = pk2((XGF), 0.0f);                                \
        unsigned long long ac2 = pk2((XGG), 0.0f);                                \
        unsigned long long ac3 = pk2((XGO), 0.0f);                                \
        _Pragma("unroll")                                                         \
        for (int j = 0; j < 25; j++) {                                            \
            unsigned long long h2 = hc[j];                                        \
            ac0 = ffma2(w0[j], h2, ac0);                                          \
            ac1 = ffma2(w1[j], h2, ac1);                                          \
            ac2 = ffma2(w2[j], h2, ac2);                                          \
            ac3 = ffma2(w3[j], h2, ac3);                                          \
        }                                                                         \
        float2 f0 = upk2(ac0), f1 = upk2(ac1), f2 = upk2(ac2), f3 = upk2(ac3);    \
        float z0 = f0.x + f0.y;                                                   \
        float z1 = f1.x + f1.y;                                                   \
        float z2 = f2.x + f2.y;                                                   \
        float z3 = f3.x + f3.y;                                                   \
        z0 += __shfl_xor_sync(0xffffffffu, z0, 1);                                \
        z1 += __shfl_xor_sync(0xffffffffu, z1, 1);                                \
        z2 += __shfl_xor_sync(0xffffffffu, z2, 1);                                \
        z3 += __shfl_xor_sync(0xffffffffu, z3, 1);                                \
        float ti = tanhapx(0.5f * z0);   /* sig(i) = .5 + .5*ti */                \
        float tf = tanhapx(0.5f * z1);                                            \
        float tg = tanhapx(z2);          /* tanh(g) */                            \
        float to = tanhapx(0.5f * z3);                                            \
        float si = fmaf(0.5f, ti, 0.5f);                                          \
        float sf = fmaf(0.5f, tf, 0.5f);                                          \
        float so = fmaf(0.5f, to, 0.5f);                                          \
        float cn = sf * creg + si * tg;                                           \
        creg = cn;                                                                \
        float hn = so * tanhapx(cn);                                              \
        if (p == 0 && act) hsf[buf ^ 1][rg] = hn;                                 \
        __syncthreads();                                                          \
        buf ^= 1;                                                                 \
    }

__global__ __launch_bounds__(256, 1) void lstm_scan(const float* __restrict__ Whh,
                                                    const float* __restrict__ Wfc,
                                                    const float* __restrict__ bfc,
                                                    float* __restrict__ out) {
    __shared__ __align__(16) float hsf[2][H];   // double-buffered h (rows 8B-aligned: 400B apart)
    __shared__ __align__(16) float swfc[3 * H];
    __shared__ float sbfc[3];
    __shared__ int s_idx;
    __shared__ int s_done;

    const int tid = threadIdx.x;
    const int rg = tid >> 1;   // 0..127 (active < 100)
    const int p = tid & 1;     // k-half
    const bool act = (rg < H);
    const bool ldx = (p == 0) && act;   // lane that injects x_gates

    for (int i = tid; i < 2 * H; i += 256) ((float*)hsf)[i] = 0.0f;
    for (int i = tid; i < 3 * H; i += 256) swfc[i] = Wfc[i];
    if (tid < 3) sbfc[tid] = bfc[tid];
    if (tid == 0) { s_idx = S / 2; s_done = 0; }

    // W_hh rows into registers: 4 gates x 25 f32x2, k in [50p, 50p+50)
    unsigned long long w0[25], w1[25], w2[25], w3[25];
    {
        const int r0 = rg, r1 = rg + H, r2 = rg + 2 * H, r3 = rg + 3 * H;
#pragma unroll
        for (int j = 0; j < 25; j++) {
            int k0 = 50 * p + 2 * j;
            float a0 = 0, b0 = 0, a1 = 0, b1 = 0, a2 = 0, b2 = 0, a3 = 0, b3 = 0;
            if (act) {
                a0 = Whh[r0 * H + k0]; b0 = Whh[r0 * H + k0 + 1];
                a1 = Whh[r1 * H + k0]; b1 = Whh[r1 * H + k0 + 1];
                a2 = Whh[r2 * H + k0]; b2 = Whh[r2 * H + k0 + 1];
                a3 = Whh[r3 * H + k0]; b3 = Whh[r3 * H + k0 + 1];
            }
            w0[j] = pk2(a0, b0);
            w1[j] = pk2(a1, b1);
            w2[j] = pk2(a2, b2);
            w3[j] = pk2(a3, b3);
        }
    }
    float creg = 0.0f;

    __syncthreads();

    int buf = 0;

    // ---------------- phase 1: sequential pass with xg prefetch ----------------
    float xi = 0, xf = 0, xg = 0, xo = 0;
    if (ldx) {
        xi = g_xg[rg];
        xf = g_xg[rg + H];
        xg = g_xg[rg + 2 * H];
        xo = g_xg[rg + 3 * H];
    }
#pragma unroll 1
    for (int t = 0; t < S; t++) {
        float ni = 0, nf = 0, ng = 0, no = 0;
        if (ldx && t + 1 < S) {
            const float* row = &g_xg[(t + 1) * G4 + rg];
            ni = row[0];
            nf = row[H];
            ng = row[2 * H];
            no = row[3 * H];
        }
        LSTM_STEP(xi, xf, xg, xo)
        xi = ni; xf = nf; xg = ng; xo = no;
    }

    // ---------------- phase 2: data-dependent scan ----------------
    float o0 = 0.0f, o1 = 0.0f;
    int consec = 0;

    int t = S / 2;
    if (ldx) {
        const float* row = &g_xg[t * G4 + rg];
        xi = row[0]; xf = row[H]; xg = row[2 * H]; xo = row[3 * H];
    }

#pragma unroll 1
    for (int it = 0; it < ITERLIM; it++) {
        const int tp = (t + 1) & (S - 1);
        const int tm = (t - 1) & (S - 1);
        float pi = 0, pf = 0, pg = 0, po = 0, mi = 0, mf = 0, mg = 0, mo = 0;
        if (ldx) {
            const float* rp = &g_xg[tp * G4 + rg];
            const float* rm = &g_xg[tm * G4 + rg];
            pi = rp[0]; pf = rp[H]; pg = rp[2 * H]; po = rp[3 * H];
            mi = rm[0]; mf = rm[H]; mg = rm[2 * H]; mo = rm[3 * H];
        }

        LSTM_STEP(xi, xf, xg, xo)
        // new h is in hsf[buf]

        if (tid < 32) {
            const float* hv = &hsf[buf][0];
            float q0 = 0.0f, q1 = 0.0f, q2 = 0.0f;
            for (int k = tid; k < H; k += 32) {
                float h = hv[k];
                q0 += swfc[k] * h;
                q1 += swfc[H + k] * h;
                q2 += swfc[2 * H + k] * h;
            }
#pragma unroll
            for (int off = 16; off; off >>= 1) {
                q0 += __shfl_down_sync(0xffffffffu, q0, off);
                q1 += __shfl_down_sync(0xffffffffu, q1, off);
                q2 += __shfl_down_sync(0xffffffffu, q2, off);
            }
            if (tid == 0) {
                q0 += sbfc[0]; q1 += sbfc[1]; q2 += sbfc[2];
                o0 = q0;
                o1 = q1;
                consec = (q1 > 0.0f) ? (consec + 1) : 0;
                if (consec > 3) s_done = 1;
                s_idx = (q2 > 0.0f) ? tp : tm;
            }
        }
        __syncthreads();
        if (s_done) break;
        const int tn = s_idx;
        const bool fwd = (tn == tp);
        xi = fwd ? pi : mi;
        xf = fwd ? pf : mf;
        xg = fwd ? pg : mg;
        xo = fwd ? po : mo;
        t = tn;
    }

    if (tid == 0) {
        out[0] = o0;
        out[1] = o1;
    }
}

// =====================================================================
// launch
// =====================================================================
extern "C" void kernel_launch(void* const* d_in, const int* in_sizes, int n_in,
                              void* d_out, int out_size) {
    const float* x   = (const float*)d_in[0];
    const float* Wih = (const float*)d_in[1];
    const float* Whh = (const float*)d_in[2];
    const float* bih = (const float*)d_in[3];
    const float* bhh = (const float*)d_in[4];
    const float* Wfc = (const float*)d_in[5];
    const float* bfc = (const float*)d_in[6];
    float* out = (float*)d_out;

    dim3 grid(S / BM, (G4 + BN - 1) / BN);
    gemm_xgates<<<grid, 256>>>(x, Wih, bih, bhh);
    lstm_scan<<<1, 256>>>(Whh, Wfc, bfc, out);
}

// round 8
// speedup vs baseline: 1.2205x; 1.1359x over previous
#include <cuda_runtime.h>

#define S        2048   // NUM_SLICE
#define INCH     2048
#define H        100
#define G4       400    // 4*H gate rows
#define ITERLIM  128

// scratch for x_gates [S][G4]; includes b_ih + b_hh
__device__ float g_xg[S * G4];

// ---------------- f32x2 packed-FMA helpers (Blackwell) ----------------
__device__ __forceinline__ unsigned long long pk2(float lo, float hi) {
    unsigned long long r;
    asm("mov.b64 %0, {%1,%2};" : "=l"(r) : "f"(lo), "f"(hi));
    return r;
}
__device__ __forceinline__ float2 upk2(unsigned long long v) {
    float2 f;
    asm("mov.b64 {%0,%1}, %2;" : "=f"(f.x), "=f"(f.y) : "l"(v));
    return f;
}
__device__ __forceinline__ unsigned long long ffma2(unsigned long long a,
                                                    unsigned long long b,
                                                    unsigned long long c) {
    unsigned long long d;
    asm("fma.rn.f32x2 %0, %1, %2, %3;" : "=l"(d) : "l"(a), "l"(b), "l"(c));
    return d;
}

// ---------------- activations (__expf ~2 ulp) ----------------
__device__ __forceinline__ float sigf(float x) {
    return __fdividef(1.0f, 1.0f + __expf(-x));
}
__device__ __forceinline__ float tanhf_(float x) {
    return __fdividef(2.0f, 1.0f + __expf(-2.0f * x)) - 1.0f;
}

// =====================================================================
// Kernel 1: x_gates[s][r] = sum_k x[k*S+s]*Wih[r*INCH+k] + bih[r] + bhh[r]
// 128(s) x 64(r) x 16(k) tiles, 112 blocks = one wave. 256 threads,
// 8s x 4r per thread (16 f32x2 accumulators).
// =====================================================================
#define BM 128
#define BN 64
#define BK 16

__global__ __launch_bounds__(256) void gemm_xgates(const float* __restrict__ x,
                                                   const float* __restrict__ Wih,
                                                   const float* __restrict__ bih,
                                                   const float* __restrict__ bhh) {
    __shared__ __align__(16) float xs[BK][BM];   // 8 KB
    __shared__ __align__(16) float ws[BN][BK];   // 4 KB

    const int tid = threadIdx.x;
    const int s0 = blockIdx.x * BM;
    const int r0 = blockIdx.y * BN;
    const int tx = tid & 15;    // 16 groups x 8 s
    const int ty = tid >> 4;    // 16 groups x 4 r

    // acc[jj][q]: r = r0+ty*4+jj, s-pair q (4 pairs = 8 s)
    unsigned long long acc[4][4];
#pragma unroll
    for (int jj = 0; jj < 4; jj++)
#pragma unroll
        for (int q = 0; q < 4; q++) acc[jj][q] = 0ull;

    // W gmem load mapping: one float4 per thread per tile
    const int wr = tid >> 2;          // 0..63 row
    const int wq = (tid & 3) * 4;     // k quad
    // x gmem load mapping: two float4 per thread per tile
    //   idx in [0,512): row kk = idx>>5, si4 = idx&31
    for (int k0 = 0; k0 < INCH; k0 += BK) {
#pragma unroll
        for (int i = 0; i < 2; i++) {
            int idx = tid + i * 256;
            int kk = idx >> 5, si4 = (idx & 31) * 4;
            *(float4*)&xs[kk][si4] = *(const float4*)&x[(k0 + kk) * S + s0 + si4];
        }
        {
            int r = r0 + wr;
            float4 wv = (r < G4) ? *(const float4*)&Wih[r * INCH + k0 + wq]
                                 : make_float4(0.f, 0.f, 0.f, 0.f);
            *(float4*)&ws[wr][wq] = wv;
        }
        __syncthreads();

#pragma unroll
        for (int kk = 0; kk < BK; kk++) {
            float4 xv0 = *(const float4*)&xs[kk][tx * 8];
            float4 xv1 = *(const float4*)&xs[kk][tx * 8 + 4];
            unsigned long long xp[4];
            xp[0] = pk2(xv0.x, xv0.y);
            xp[1] = pk2(xv0.z, xv0.w);
            xp[2] = pk2(xv1.x, xv1.y);
            xp[3] = pk2(xv1.z, xv1.w);
#pragma unroll
            for (int jj = 0; jj < 4; jj++) {
                float wv = ws[ty * 4 + jj][kk];
                unsigned long long wd = pk2(wv, wv);
#pragma unroll
                for (int q = 0; q < 4; q++)
                    acc[jj][q] = ffma2(xp[q], wd, acc[jj][q]);
            }
        }
        __syncthreads();
    }

#pragma unroll
    for (int jj = 0; jj < 4; jj++) {
        int r = r0 + ty * 4 + jj;
        if (r < G4) {
            float bb = bih[r] + bhh[r];
            int sb = s0 + tx * 8;
#pragma unroll
            for (int q = 0; q < 4; q++) {
                float2 v = upk2(acc[jj][q]);
                g_xg[(sb + 2 * q + 0) * G4 + r] = v.x + bb;
                g_xg[(sb + 2 * q + 1) * G4 + r] = v.y + bb;
            }
        }
    }
}

// =====================================================================
// Kernel 2: persistent single-CTA LSTM scan — R3 structure verbatim,
// minus the per-step bias adds (biases folded into g_xg).
// 256 threads: rg = tid>>1 (active < 100), p = tid&1 (k-half of 50).
// =====================================================================

#define LSTM_STEP(XGA, XGB)                                                       \
    {                                                                             \
        const unsigned long long* hc =                                            \
            (const unsigned long long*)&hs[buf][0] + 25 * p;                      \
        unsigned long long ac0 = 0ull, ac1 = 0ull, ac2 = 0ull, ac3 = 0ull;        \
        _Pragma("unroll")                                                         \
        for (int j = 0; j < 25; j++) {                                            \
            unsigned long long h2 = hc[j];                                        \
            ac0 = ffma2(w0[j], h2, ac0);                                          \
            ac1 = ffma2(w1[j], h2, ac1);                                          \
            ac2 = ffma2(w2[j], h2, ac2);                                          \
            ac3 = ffma2(w3[j], h2, ac3);                                          \
        }                                                                         \
        float2 f0 = upk2(ac0), f1 = upk2(ac1), f2 = upk2(ac2), f3 = upk2(ac3);    \
        float z0 = f0.x + f0.y;                                                   \
        float z1 = f1.x + f1.y;                                                   \
        float z2 = f2.x + f2.y;                                                   \
        float z3 = f3.x + f3.y;                                                   \
        float zA = p ? z1 : z0;                                                   \
        float zB = p ? z3 : z2;                                                   \
        float sA = p ? z0 : z1;                                                   \
        float sB = p ? z2 : z3;                                                   \
        zA += __shfl_xor_sync(0xffffffffu, sA, 1);                                \
        zB += __shfl_xor_sync(0xffffffffu, sB, 1);                                \
        zA += (XGA);                                                              \
        zB += (XGB);                                                              \
        /* lane0: nlA=sig(i), nlB=tanh(g); lane1: nlA=sig(f), nlB=sig(o) */       \
        float nlA = sigf(zA);                                                     \
        float aB  = p ? -zB : -(zB + zB);                                         \
        float eB  = __expf(aB);                                                   \
        float sB2 = __fdividef(1.0f, 1.0f + eB);                                  \
        float nlB = p ? sB2 : (sB2 + sB2 - 1.0f);                                 \
        float gA = __shfl_xor_sync(0xffffffffu, nlA, 1);                          \
        float gB = __shfl_xor_sync(0xffffffffu, nlB, 1);                          \
        if (p == 0 && act) {                                                      \
            /* gA = sig(f), gB = sig(o), nlA = sig(i), nlB = tanh(g) */           \
            float cn = gA * creg + nlA * nlB;                                     \
            creg = cn;                                                            \
            float hn = gB * tanhf_(cn);                                           \
            hs[buf ^ 1][rg] = hn;                                                 \
        }                                                                         \
        __syncthreads();                                                          \
        buf ^= 1;                                                                 \
    }

__global__ __launch_bounds__(256, 1) void lstm_scan(const float* __restrict__ Whh,
                                                    const float* __restrict__ Wfc,
                                                    const float* __restrict__ bfc,
                                                    float* __restrict__ out) {
    __shared__ __align__(16) float hs[2][H];   // double-buffered h
    __shared__ float swfc[3 * H];
    __shared__ float sbfc[3];
    __shared__ int s_idx;
    __shared__ int s_done;

    const int tid = threadIdx.x;
    const int rg = tid >> 1;   // 0..127 (active < 100)
    const int p = tid & 1;     // k-half
    const bool act = (rg < H);

    const int rA = p * H + rg;         // gate p row
    const int rB = (p + 2) * H + rg;   // gate p+2 row

    for (int i = tid; i < 2 * H; i += 256) ((float*)hs)[i] = 0.0f;
    for (int i = tid; i < 3 * H; i += 256) swfc[i] = Wfc[i];
    if (tid < 3) sbfc[tid] = bfc[tid];
    if (tid == 0) { s_idx = S / 2; s_done = 0; }

    // W_hh into registers: 4 gates x 25 f32x2, k in [50p, 50p+50)
    unsigned long long w0[25], w1[25], w2[25], w3[25];
    {
        const int r0 = rg, r1 = rg + H, r2 = rg + 2 * H, r3 = rg + 3 * H;
#pragma unroll
        for (int j = 0; j < 25; j++) {
            int k0 = 50 * p + 2 * j;
            float a0 = 0, b0 = 0, a1 = 0, b1 = 0, a2 = 0, b2 = 0, a3 = 0, b3 = 0;
            if (act) {
                a0 = Whh[r0 * H + k0]; b0 = Whh[r0 * H + k0 + 1];
                a1 = Whh[r1 * H + k0]; b1 = Whh[r1 * H + k0 + 1];
                a2 = Whh[r2 * H + k0]; b2 = Whh[r2 * H + k0 + 1];
                a3 = Whh[r3 * H + k0]; b3 = Whh[r3 * H + k0 + 1];
            }
            w0[j] = pk2(a0, b0);
            w1[j] = pk2(a1, b1);
            w2[j] = pk2(a2, b2);
            w3[j] = pk2(a3, b3);
        }
    }
    float creg = 0.0f;

    __syncthreads();

    int buf = 0;

    // ---------------- phase 1: sequential pass with xg prefetch ----------------
    float xgA = act ? g_xg[rA] : 0.0f;   // t = 0
    float xgB = act ? g_xg[rB] : 0.0f;
#pragma unroll 1
    for (int t = 0; t < S; t++) {
        float xgA_n = 0.0f, xgB_n = 0.0f;
        if (act && t + 1 < S) {
            xgA_n = g_xg[(t + 1) * G4 + rA];
            xgB_n = g_xg[(t + 1) * G4 + rB];
        }
        LSTM_STEP(xgA, xgB)
        xgA = xgA_n;
        xgB = xgB_n;
    }

    // ---------------- phase 2: data-dependent scan ----------------
    float o0 = 0.0f, o1 = 0.0f;
    int consec = 0;

    int t = S / 2;
    xgA = act ? g_xg[t * G4 + rA] : 0.0f;
    xgB = act ? g_xg[t * G4 + rB] : 0.0f;

#pragma unroll 1
    for (int it = 0; it < ITERLIM; it++) {
        const int tp = (t + 1) & (S - 1);
        const int tm = (t - 1) & (S - 1);
        float pA = 0, pB = 0, mA = 0, mB = 0;
        if (act) {
            pA = g_xg[tp * G4 + rA];
            pB = g_xg[tp * G4 + rB];
            mA = g_xg[tm * G4 + rA];
            mB = g_xg[tm * G4 + rB];
        }

        LSTM_STEP(xgA, xgB)
        // new h is in hs[buf]

        if (tid < 32) {
            const float* hv = &hs[buf][0];
            float q0 = 0.0f, q1 = 0.0f, q2 = 0.0f;
            for (int k = tid; k < H; k += 32) {
                float h = hv[k];
                q0 += swfc[k] * h;
                q1 += swfc[H + k] * h;
                q2 += swfc[2 * H + k] * h;
            }
#pragma unroll
            for (int off = 16; off; off >>= 1) {
                q0 += __shfl_down_sync(0xffffffffu, q0, off);
                q1 += __shfl_down_sync(0xffffffffu, q1, off);
                q2 += __shfl_down_sync(0xffffffffu, q2, off);
            }
            if (tid == 0) {
                q0 += sbfc[0]; q1 += sbfc[1]; q2 += sbfc[2];
                o0 = q0;
                o1 = q1;
                consec = (q1 > 0.0f) ? (consec + 1) : 0;
                if (consec > 3) s_done = 1;
                s_idx = (q2 > 0.0f) ? tp : tm;
            }
        }
        __syncthreads();
        if (s_done) break;
        const int tn = s_idx;
        const bool fwd = (tn == tp);
        xgA = fwd ? pA : mA;
        xgB = fwd ? pB : mB;
        t = tn;
    }

    if (tid == 0) {
        out[0] = o0;
        out[1] = o1;
    }
}

// =====================================================================
// launch
// =====================================================================
extern "C" void kernel_launch(void* const* d_in, const int* in_sizes, int n_in,
                              void* d_out, int out_size) {
    const float* x   = (const float*)d_in[0];
    const float* Wih = (const float*)d_in[1];
    const float* Whh = (const float*)d_in[2];
    const float* bih = (const float*)d_in[3];
    const float* bhh = (const float*)d_in[4];
    const float* Wfc = (const float*)d_in[5];
    const float* bfc = (const float*)d_in[6];
    float* out = (float*)d_out;

    dim3 grid(S / BM, (G4 + BN - 1) / BN);
    gemm_xgates<<<grid, 256>>>(x, Wih, bih, bhh);
    lstm_scan<<<1, 256>>>(Whh, Wfc, bfc, out);
}

// round 9
// speedup vs baseline: 1.2499x; 1.0241x over previous
#include <cuda_runtime.h>

#define S        2048   // NUM_SLICE
#define INCH     2048
#define H        100
#define G4       400    // 4*H gate rows
#define ITERLIM  128

// scratch for x_gates [S][G4]; includes b_ih + b_hh
__device__ float g_xg[S * G4];

// ---------------- f32x2 packed-FMA helpers (Blackwell) ----------------
__device__ __forceinline__ unsigned long long pk2(float lo, float hi) {
    unsigned long long r;
    asm("mov.b64 %0, {%1,%2};" : "=l"(r) : "f"(lo), "f"(hi));
    return r;
}
__device__ __forceinline__ float2 upk2(unsigned long long v) {
    float2 f;
    asm("mov.b64 {%0,%1}, %2;" : "=f"(f.x), "=f"(f.y) : "l"(v));
    return f;
}
__device__ __forceinline__ unsigned long long ffma2(unsigned long long a,
                                                    unsigned long long b,
                                                    unsigned long long c) {
    unsigned long long d;
    asm("fma.rn.f32x2 %0, %1, %2, %3;" : "=l"(d) : "l"(a), "l"(b), "l"(c));
    return d;
}

// ---------------- activations (__expf ~2 ulp) ----------------
__device__ __forceinline__ float sigf(float x) {
    return __fdividef(1.0f, 1.0f + __expf(-x));
}
__device__ __forceinline__ float tanhf_(float x) {
    return __fdividef(2.0f, 1.0f + __expf(-2.0f * x)) - 1.0f;
}

// =====================================================================
// Kernel 1: x_gates[s][r] = sum_k x[k*S+s]*Wih[r*INCH+k] + bih[r] + bhh[r]
// 128(s) x 64(r) x 16(k) tiles, 112 blocks = one wave. (R8, unchanged)
// =====================================================================
#define BM 128
#define BN 64
#define BK 16

__global__ __launch_bounds__(256) void gemm_xgates(const float* __restrict__ x,
                                                   const float* __restrict__ Wih,
                                                   const float* __restrict__ bih,
                                                   const float* __restrict__ bhh) {
    __shared__ __align__(16) float xs[BK][BM];   // 8 KB
    __shared__ __align__(16) float ws[BN][BK];   // 4 KB

    const int tid = threadIdx.x;
    const int s0 = blockIdx.x * BM;
    const int r0 = blockIdx.y * BN;
    const int tx = tid & 15;    // 16 groups x 8 s
    const int ty = tid >> 4;    // 16 groups x 4 r

    unsigned long long acc[4][4];
#pragma unroll
    for (int jj = 0; jj < 4; jj++)
#pragma unroll
        for (int q = 0; q < 4; q++) acc[jj][q] = 0ull;

    const int wr = tid >> 2;          // 0..63 row
    const int wq = (tid & 3) * 4;     // k quad
    for (int k0 = 0; k0 < INCH; k0 += BK) {
#pragma unroll
        for (int i = 0; i < 2; i++) {
            int idx = tid + i * 256;
            int kk = idx >> 5, si4 = (idx & 31) * 4;
            *(float4*)&xs[kk][si4] = *(const float4*)&x[(k0 + kk) * S + s0 + si4];
        }
        {
            int r = r0 + wr;
            float4 wv = (r < G4) ? *(const float4*)&Wih[r * INCH + k0 + wq]
                                 : make_float4(0.f, 0.f, 0.f, 0.f);
            *(float4*)&ws[wr][wq] = wv;
        }
        __syncthreads();

#pragma unroll
        for (int kk = 0; kk < BK; kk++) {
            float4 xv0 = *(const float4*)&xs[kk][tx * 8];
            float4 xv1 = *(const float4*)&xs[kk][tx * 8 + 4];
            unsigned long long xp[4];
            xp[0] = pk2(xv0.x, xv0.y);
            xp[1] = pk2(xv0.z, xv0.w);
            xp[2] = pk2(xv1.x, xv1.y);
            xp[3] = pk2(xv1.z, xv1.w);
#pragma unroll
            for (int jj = 0; jj < 4; jj++) {
                float wv = ws[ty * 4 + jj][kk];
                unsigned long long wd = pk2(wv, wv);
#pragma unroll
                for (int q = 0; q < 4; q++)
                    acc[jj][q] = ffma2(xp[q], wd, acc[jj][q]);
            }
        }
        __syncthreads();
    }

#pragma unroll
    for (int jj = 0; jj < 4; jj++) {
        int r = r0 + ty * 4 + jj;
        if (r < G4) {
            float bb = bih[r] + bhh[r];
            int sb = s0 + tx * 8;
#pragma unroll
            for (int q = 0; q < 4; q++) {
                float2 v = upk2(acc[jj][q]);
                g_xg[(sb + 2 * q + 0) * G4 + r] = v.x + bb;
                g_xg[(sb + 2 * q + 1) * G4 + r] = v.y + bb;
            }
        }
    }
}

// =====================================================================
// Kernel 2: persistent single-CTA LSTM scan — R3 structure, with h stored
// in two 256B-aligned half-regions per buffer so each thread's 25 f32x2
// operands load as 12x LDS.128 + 1x LDS.64 (no repack MOVs).
//   buffer b base = b*128 floats; h[0..49] at +0, h[50..99] at +64 floats.
// 256 threads: rg = tid>>1 (active < 100), p = tid&1 (k-half of 50).
// =====================================================================

#define LSTM_STEP(XGA, XGB)                                                       \
    {                                                                             \
        const ulonglong2* hc2 =                                                   \
            (const ulonglong2*)(hsf + buf * 128 + p * 64);                        \
        unsigned long long ac0 = 0ull, ac1 = 0ull, ac2 = 0ull, ac3 = 0ull;        \
        _Pragma("unroll")                                                         \
        for (int j = 0; j < 12; j++) {                                            \
            ulonglong2 u = hc2[j];                                                \
            ac0 = ffma2(w0[2 * j], u.x, ac0);                                     \
            ac1 = ffma2(w1[2 * j], u.x, ac1);                                     \
            ac2 = ffma2(w2[2 * j], u.x, ac2);                                     \
            ac3 = ffma2(w3[2 * j], u.x, ac3);                                     \
            ac0 = ffma2(w0[2 * j + 1], u.y, ac0);                                 \
            ac1 = ffma2(w1[2 * j + 1], u.y, ac1);                                 \
            ac2 = ffma2(w2[2 * j + 1], u.y, ac2);                                 \
            ac3 = ffma2(w3[2 * j + 1], u.y, ac3);                                 \
        }                                                                         \
        {                                                                         \
            unsigned long long last = ((const unsigned long long*)hc2)[24];       \
            ac0 = ffma2(w0[24], last, ac0);                                       \
            ac1 = ffma2(w1[24], last, ac1);                                       \
            ac2 = ffma2(w2[24], last, ac2);                                       \
            ac3 = ffma2(w3[24], last, ac3);                                       \
        }                                                                         \
        float2 f0 = upk2(ac0), f1 = upk2(ac1), f2 = upk2(ac2), f3 = upk2(ac3);    \
        float z0 = f0.x + f0.y;                                                   \
        float z1 = f1.x + f1.y;                                                   \
        float z2 = f2.x + f2.y;                                                   \
        float z3 = f3.x + f3.y;                                                   \
        float zA = p ? z1 : z0;                                                   \
        float zB = p ? z3 : z2;                                                   \
        float sA = p ? z0 : z1;                                                   \
        float sB = p ? z2 : z3;                                                   \
        zA += __shfl_xor_sync(0xffffffffu, sA, 1);                                \
        zB += __shfl_xor_sync(0xffffffffu, sB, 1);                                \
        zA += (XGA);                                                              \
        zB += (XGB);                                                              \
        /* lane0: nlA=sig(i), nlB=tanh(g); lane1: nlA=sig(f), nlB=sig(o) */       \
        float nlA = sigf(zA);                                                     \
        float aB  = p ? -zB : -(zB + zB);                                         \
        float eB  = __expf(aB);                                                   \
        float sB2 = __fdividef(1.0f, 1.0f + eB);                                  \
        float nlB = p ? sB2 : (sB2 + sB2 - 1.0f);                                 \
        float gA = __shfl_xor_sync(0xffffffffu, nlA, 1);                          \
        float gB = __shfl_xor_sync(0xffffffffu, nlB, 1);                          \
        if (p == 0 && act) {                                                      \
            /* gA = sig(f), gB = sig(o), nlA = sig(i), nlB = tanh(g) */           \
            float cn = gA * creg + nlA * nlB;                                     \
            creg = cn;                                                            \
            float hn = gB * tanhf_(cn);                                           \
            hsf[(buf ^ 1) * 128 + hpos] = hn;                                     \
        }                                                                         \
        __syncthreads();                                                          \
        buf ^= 1;                                                                 \
    }

__global__ __launch_bounds__(256, 1) void lstm_scan(const float* __restrict__ Whh,
                                                    const float* __restrict__ Wfc,
                                                    const float* __restrict__ bfc,
                                                    float* __restrict__ out) {
    __shared__ __align__(16) float hsf[2 * 128];  // split-region double buffer
    __shared__ float swfc[3 * H];
    __shared__ float sbfc[3];
    __shared__ int s_idx;
    __shared__ int s_done;

    const int tid = threadIdx.x;
    const int rg = tid >> 1;   // 0..127 (active < 100)
    const int p = tid & 1;     // k-half
    const bool act = (rg < H);
    const int hpos = (rg < 50) ? rg : (64 + rg - 50);   // split-layout slot

    const int rA = p * H + rg;         // gate p row
    const int rB = (p + 2) * H + rg;   // gate p+2 row

    for (int i = tid; i < 2 * 128; i += 256) hsf[i] = 0.0f;
    for (int i = tid; i < 3 * H; i += 256) swfc[i] = Wfc[i];
    if (tid < 3) sbfc[tid] = bfc[tid];
    if (tid == 0) { s_idx = S / 2; s_done = 0; }

    // W_hh into registers: 4 gates x 25 f32x2, k in [50p, 50p+50)
    unsigned long long w0[25], w1[25], w2[25], w3[25];
    {
        const int r0 = rg, r1 = rg + H, r2 = rg + 2 * H, r3 = rg + 3 * H;
#pragma unroll
        for (int j = 0; j < 25; j++) {
            int k0 = 50 * p + 2 * j;
            float a0 = 0, b0 = 0, a1 = 0, b1 = 0, a2 = 0, b2 = 0, a3 = 0, b3 = 0;
            if (act) {
                a0 = Whh[r0 * H + k0]; b0 = Whh[r0 * H + k0 + 1];
                a1 = Whh[r1 * H + k0]; b1 = Whh[r1 * H + k0 + 1];
                a2 = Whh[r2 * H + k0]; b2 = Whh[r2 * H + k0 + 1];
                a3 = Whh[r3 * H + k0]; b3 = Whh[r3 * H + k0 + 1];
            }
            w0[j] = pk2(a0, b0);
            w1[j] = pk2(a1, b1);
            w2[j] = pk2(a2, b2);
            w3[j] = pk2(a3, b3);
        }
    }
    float creg = 0.0f;

    __syncthreads();

    int buf = 0;

    // ---------------- phase 1: sequential pass with xg prefetch ----------------
    float xgA = act ? g_xg[rA] : 0.0f;   // t = 0
    float xgB = act ? g_xg[rB] : 0.0f;
#pragma unroll 1
    for (int t = 0; t < S; t++) {
        float xgA_n = 0.0f, xgB_n = 0.0f;
        if (act && t + 1 < S) {
            xgA_n = g_xg[(t + 1) * G4 + rA];
            xgB_n = g_xg[(t + 1) * G4 + rB];
        }
        LSTM_STEP(xgA, xgB)
        xgA = xgA_n;
        xgB = xgB_n;
    }

    // ---------------- phase 2: data-dependent scan ----------------
    float o0 = 0.0f, o1 = 0.0f;
    int consec = 0;

    int t = S / 2;
    xgA = act ? g_xg[t * G4 + rA] : 0.0f;
    xgB = act ? g_xg[t * G4 + rB] : 0.0f;

#pragma unroll 1
    for (int it = 0; it < ITERLIM; it++) {
        const int tp = (t + 1) & (S - 1);
        const int tm = (t - 1) & (S - 1);
        float pA = 0, pB = 0, mA = 0, mB = 0;
        if (act) {
            pA = g_xg[tp * G4 + rA];
            pB = g_xg[tp * G4 + rB];
            mA = g_xg[tm * G4 + rA];
            mB = g_xg[tm * G4 + rB];
        }

        LSTM_STEP(xgA, xgB)
        // new h is in hsf[buf]

        if (tid < 32) {
            const float* hv = &hsf[buf * 128];
            float q0 = 0.0f, q1 = 0.0f, q2 = 0.0f;
            for (int k = tid; k < H; k += 32) {
                float h = hv[(k < 50) ? k : (64 + k - 50)];
                q0 += swfc[k] * h;
                q1 += swfc[H + k] * h;
                q2 += swfc[2 * H + k] * h;
            }
#pragma unroll
            for (int off = 16; off; off >>= 1) {
                q0 += __shfl_down_sync(0xffffffffu, q0, off);
                q1 += __shfl_down_sync(0xffffffffu, q1, off);
                q2 += __shfl_down_sync(0xffffffffu, q2, off);
            }
            if (tid == 0) {
                q0 += sbfc[0]; q1 += sbfc[1]; q2 += sbfc[2];
                o0 = q0;
                o1 = q1;
                consec = (q1 > 0.0f) ? (consec + 1) : 0;
                if (consec > 3) s_done = 1;
                s_idx = (q2 > 0.0f) ? tp : tm;
            }
        }
        __syncthreads();
        if (s_done) break;
        const int tn = s_idx;
        const bool fwd = (tn == tp);
        xgA = fwd ? pA : mA;
        xgB = fwd ? pB : mB;
        t = tn;
    }

    if (tid == 0) {
        out[0] = o0;
        out[1] = o1;
    }
}

// =====================================================================
// launch
// =====================================================================
extern "C" void kernel_launch(void* const* d_in, const int* in_sizes, int n_in,
                              void* d_out, int out_size) {
    const float* x   = (const float*)d_in[0];
    const float* Wih = (const float*)d_in[1];
    const float* Whh = (const float*)d_in[2];
    const float* bih = (const float*)d_in[3];
    const float* bhh = (const float*)d_in[4];
    const float* Wfc = (const float*)d_in[5];
    const float* bfc = (const float*)d_in[6];
    float* out = (float*)d_out;

    dim3 grid(S / BM, (G4 + BN - 1) / BN);
    gemm_xgates<<<grid, 256>>>(x, Wih, bih, bhh);
    lstm_scan<<<1, 256>>>(Whh, Wfc, bfc, out);
}

// round 12
// speedup vs baseline: 1.2550x; 1.0041x over previous
#include <cuda_runtime.h>

#define S        2048   // NUM_SLICE
#define INCH     2048
#define H        100
#define G4       400    // 4*H gate rows
#define ITERLIM  128
#define HSTRIDE  112    // h buffer stride (100 + pad, 16B-aligned)

// scratch for x_gates [S][G4]; includes b_ih + b_hh
__device__ float g_xg[S * G4];

// ---------------- f32x2 packed-FMA helpers (Blackwell) ----------------
__device__ __forceinline__ unsigned long long pk2(float lo, float hi) {
    unsigned long long r;
    asm("mov.b64 %0, {%1,%2};" : "=l"(r) : "f"(lo), "f"(hi));
    return r;
}
__device__ __forceinline__ float2 upk2(unsigned long long v) {
    float2 f;
    asm("mov.b64 {%0,%1}, %2;" : "=f"(f.x), "=f"(f.y) : "l"(v));
    return f;
}
__device__ __forceinline__ unsigned long long ffma2(unsigned long long a,
                                                    unsigned long long b,
                                                    unsigned long long c) {
    unsigned long long d;
    asm("fma.rn.f32x2 %0, %1, %2, %3;" : "=l"(d) : "l"(a), "l"(b), "l"(c));
    return d;
}

// ---------------- activations (__expf ~2 ulp) ----------------
__device__ __forceinline__ float sigf(float x) {
    return __fdividef(1.0f, 1.0f + __expf(-x));
}
__device__ __forceinline__ float tanhf_(float x) {
    return __fdividef(2.0f, 1.0f + __expf(-2.0f * x)) - 1.0f;
}

// =====================================================================
// Kernel 1: x_gates GEMM (R8, unchanged). Adds bih+bhh.
// =====================================================================
#define BM 128
#define BN 64
#define BK 16

__global__ __launch_bounds__(256) void gemm_xgates(const float* __restrict__ x,
                                                   const float* __restrict__ Wih,
                                                   const float* __restrict__ bih,
                                                   const float* __restrict__ bhh) {
    __shared__ __align__(16) float xs[BK][BM];
    __shared__ __align__(16) float ws[BN][BK];

    const int tid = threadIdx.x;
    const int s0 = blockIdx.x * BM;
    const int r0 = blockIdx.y * BN;
    const int tx = tid & 15;
    const int ty = tid >> 4;

    unsigned long long acc[4][4];
#pragma unroll
    for (int jj = 0; jj < 4; jj++)
#pragma unroll
        for (int q = 0; q < 4; q++) acc[jj][q] = 0ull;

    const int wr = tid >> 2;
    const int wq = (tid & 3) * 4;
    for (int k0 = 0; k0 < INCH; k0 += BK) {
#pragma unroll
        for (int i = 0; i < 2; i++) {
            int idx = tid + i * 256;
            int kk = idx >> 5, si4 = (idx & 31) * 4;
            *(float4*)&xs[kk][si4] = *(const float4*)&x[(k0 + kk) * S + s0 + si4];
        }
        {
            int r = r0 + wr;
            float4 wv = (r < G4) ? *(const float4*)&Wih[r * INCH + k0 + wq]
                                 : make_float4(0.f, 0.f, 0.f, 0.f);
            *(float4*)&ws[wr][wq] = wv;
        }
        __syncthreads();

#pragma unroll
        for (int kk = 0; kk < BK; kk++) {
            float4 xv0 = *(const float4*)&xs[kk][tx * 8];
            float4 xv1 = *(const float4*)&xs[kk][tx * 8 + 4];
            unsigned long long xp[4];
            xp[0] = pk2(xv0.x, xv0.y);
            xp[1] = pk2(xv0.z, xv0.w);
            xp[2] = pk2(xv1.x, xv1.y);
            xp[3] = pk2(xv1.z, xv1.w);
#pragma unroll
            for (int jj = 0; jj < 4; jj++) {
                float wv = ws[ty * 4 + jj][kk];
                unsigned long long wd = pk2(wv, wv);
#pragma unroll
                for (int q = 0; q < 4; q++)
                    acc[jj][q] = ffma2(xp[q], wd, acc[jj][q]);
            }
        }
        __syncthreads();
    }

#pragma unroll
    for (int jj = 0; jj < 4; jj++) {
        int r = r0 + ty * 4 + jj;
        if (r < G4) {
            float bb = bih[r] + bhh[r];
            int sb = s0 + tx * 8;
#pragma unroll
            for (int q = 0; q < 4; q++) {
                float2 v = upk2(acc[jj][q]);
                g_xg[(sb + 2 * q + 0) * G4 + r] = v.x + bb;
                g_xg[(sb + 2 * q + 1) * G4 + r] = v.y + bb;
            }
        }
    }
}

// =====================================================================
// Kernel 2: persistent single-CTA LSTM scan, warp-specialized balance.
//   Warps 0-3 (A): rows 0-63, pair k-split 50/50, 100 ffma2/lane.
//   Warps 4-7 (B): rows 64-99, 9 triples/warp, k-split 34/34/32,
//                  68 ffma2/lane. SMSP_i = warp i + warp i+4 -> 504 cyc.
// =====================================================================

// Both-path step. XGA/XGB: per-lane gate-injection values (0 where unused).
#define LSTM_STEP(XGA, XGB)                                                       \
    {                                                                             \
        const unsigned long long* hb =                                            \
            (const unsigned long long*)(hsf + buf * HSTRIDE);                     \
        float z0, z1, z2, z3;                                                     \
        if (isA) {                                                                \
            const unsigned long long* hc = hb + 25 * p;                           \
            unsigned long long a0 = 0ull, a1 = 0ull, a2 = 0ull, a3 = 0ull;        \
            _Pragma("unroll")                                                     \
            for (int j = 0; j < 25; j++) {                                        \
                unsigned long long h2 = hc[j];                                    \
                a0 = ffma2(w0[j], h2, a0);                                        \
                a1 = ffma2(w1[j], h2, a1);                                        \
                a2 = ffma2(w2[j], h2, a2);                                        \
                a3 = ffma2(w3[j], h2, a3);                                        \
            }                                                                     \
            float2 f0 = upk2(a0), f1 = upk2(a1), f2 = upk2(a2), f3 = upk2(a3);    \
            z0 = f0.x + f0.y; z1 = f1.x + f1.y;                                   \
            z2 = f2.x + f2.y; z3 = f3.x + f3.y;                                   \
            /* pair exchange: lane p keeps gates {p, p+2} */                      \
            float zA = p ? z1 : z0;                                               \
            float zB = p ? z3 : z2;                                               \
            float sA = p ? z0 : z1;                                               \
            float sB = p ? z2 : z3;                                               \
            zA += __shfl_xor_sync(0xffffffffu, sA, 1);                            \
            zB += __shfl_xor_sync(0xffffffffu, sB, 1);                            \
            zA += (XGA);                                                          \
            zB += (XGB);                                                          \
            float nlA = sigf(zA);                                                 \
            float aB  = p ? -zB : -(zB + zB);                                     \
            float eB  = __expf(aB);                                               \
            float sB2 = __fdividef(1.0f, 1.0f + eB);                              \
            float nlB = p ? sB2 : (sB2 + sB2 - 1.0f);                             \
            float gA = __shfl_xor_sync(0xffffffffu, nlA, 1);                      \
            float gB = __shfl_xor_sync(0xffffffffu, nlB, 1);                      \
            if (p == 0) {                                                         \
                float cn = gA * creg + nlA * nlB;                                 \
                creg = cn;                                                        \
                float hn = gB * tanhf_(cn);                                       \
                hsf[(buf ^ 1) * HSTRIDE + row] = hn;                              \
            }                                                                     \
        } else {                                                                  \
            const unsigned long long* hc = hb + hoff;                            \
            unsigned long long a0 = 0ull, a1 = 0ull, a2 = 0ull, a3 = 0ull;        \
            _Pragma("unroll")                                                     \
            for (int j = 0; j < 17; j++) {                                        \
                unsigned long long h2 = hc[j];                                    \
                a0 = ffma2(w0[j], h2, a0);                                        \
                a1 = ffma2(w1[j], h2, a1);                                        \
                a2 = ffma2(w2[j], h2, a2);                                        \
                a3 = ffma2(w3[j], h2, a3);                                        \
            }                                                                     \
            float2 f0 = upk2(a0), f1 = upk2(a1), f2 = upk2(a2), f3 = upk2(a3);    \
            z0 = f0.x + f0.y; z1 = f1.x + f1.y;                                   \
            z2 = f2.x + f2.y; z3 = f3.x + f3.y;                                   \
            /* packed triple reduce: m0 keeps {0,2}, m1 keeps {1,3} */            \
            float snd1 = (m == 1) ? z0 : z1;                                      \
            float snd2 = (m == 1) ? z2 : z3;                                      \
            float snd3 = (m == 2) ? z0 : z1;                                      \
            float snd4 = (m == 2) ? z2 : z3;                                      \
            float r1 = __shfl_sync(0xffffffffu, snd1, idx1);                      \
            float r2 = __shfl_sync(0xffffffffu, snd2, idx1);                      \
            float r3 = __shfl_sync(0xffffffffu, snd3, idx2);                      \
            float r4 = __shfl_sync(0xffffffffu, snd4, idx2);                      \
            float zA = ((m == 1) ? z1 : z0) + r1 + r3;                            \
            float zB = ((m == 1) ? z3 : z2) + r2 + r4;                            \
            zA += (XGA);                                                          \
            zB += (XGB);                                                          \
            float nlA = sigf(zA);                                                 \
            float aB  = (m == 1) ? -zB : -(zB + zB);                              \
            float eB  = __expf(aB);                                               \
            float sB2 = __fdividef(1.0f, 1.0f + eB);                              \
            float nlB = (m == 1) ? sB2 : (sB2 + sB2 - 1.0f);                      \
            float gA = __shfl_sync(0xffffffffu, nlA, b3 + 1);                     \
            float gB = __shfl_sync(0xffffffffu, nlB, b3 + 1);                     \
            if (m == 0 && act) {                                                  \
                float cn = gA * creg + nlA * nlB;                                 \
                creg = cn;                                                        \
                float hn = gB * tanhf_(cn);                                       \
                hsf[(buf ^ 1) * HSTRIDE + row] = hn;                              \
            }                                                                     \
        }                                                                         \
        __syncthreads();                                                          \
        buf ^= 1;                                                                 \
    }

__global__ __launch_bounds__(256, 1) void lstm_scan(const float* __restrict__ Whh,
                                                    const float* __restrict__ Wfc,
                                                    const float* __restrict__ bfc,
                                                    float* __restrict__ out) {
    __shared__ __align__(16) float hsf[2 * HSTRIDE];   // double buffer + zero pad
    __shared__ float swfc[3 * H];
    __shared__ float sbfc[3];
    __shared__ int s_idx;
    __shared__ int s_done;

    const int tid = threadIdx.x;
    const int wid = tid >> 5;
    const int lane = tid & 31;
    const bool isA = (wid < 4);

    // ---- lane geometry ----
    // A: pair split
    const int pA_row = wid * 16 + (lane >> 1);     // rows 0..63
    const int p = lane & 1;
    // B: triple split
    const int trip = lane / 3;                     // 0..10 (valid < 9)
    const int m = lane - 3 * trip;                 // 0,1,2
    const int b3 = 3 * trip;                       // triple base lane
    const int bB_row = 64 + (wid - 4) * 9 + trip;  // rows 64..99 when trip<9
    const int idx1 = b3 + (m == 2 ? 0 : m + 1);
    const int idx2 = b3 + (m == 0 ? 2 : m - 1);
    const int hoff = (m == 0) ? 0 : (m == 1) ? 17 : 34;   // ull offset into h

    const int row = isA ? pA_row : bB_row;
    const bool act = isA ? true : (trip < 9);
    // xg lane roles: gate-low selector
    const int gsel = isA ? p : ((m == 1) ? 1 : 0);
    const bool ldx = isA ? true : (act && m < 2);
    const int rA = gsel * H + row;        // gate gsel
    const int rB = (gsel + 2) * H + row;  // gate gsel+2

    for (int i = tid; i < 2 * HSTRIDE; i += 256) hsf[i] = 0.0f;
    for (int i = tid; i < 3 * H; i += 256) swfc[i] = Wfc[i];
    if (tid < 3) sbfc[tid] = bfc[tid];
    if (tid == 0) { s_idx = S / 2; s_done = 0; }

    // ---- weights into registers ----
    unsigned long long w0[25], w1[25], w2[25], w3[25];
    {
        const int r0 = row, r1 = row + H, r2 = row + 2 * H, r3 = row + 3 * H;
        if (isA) {
#pragma unroll
            for (int j = 0; j < 25; j++) {
                int k0 = 50 * p + 2 * j;
                w0[j] = pk2(Whh[r0 * H + k0], Whh[r0 * H + k0 + 1]);
                w1[j] = pk2(Whh[r1 * H + k0], Whh[r1 * H + k0 + 1]);
                w2[j] = pk2(Whh[r2 * H + k0], Whh[r2 * H + k0 + 1]);
                w3[j] = pk2(Whh[r3 * H + k0], Whh[r3 * H + k0 + 1]);
            }
        } else {
#pragma unroll
            for (int j = 0; j < 17; j++) {
                int k0 = 2 * (hoff + j);
                bool v = act && (k0 < H);   // k0+1 <= 99 whenever k0 < 100 (k0 even)
                w0[j] = v ? pk2(Whh[r0 * H + k0], Whh[r0 * H + k0 + 1]) : 0ull;
                w1[j] = v ? pk2(Whh[r1 * H + k0], Whh[r1 * H + k0 + 1]) : 0ull;
                w2[j] = v ? pk2(Whh[r2 * H + k0], Whh[r2 * H + k0 + 1]) : 0ull;
                w3[j] = v ? pk2(Whh[r3 * H + k0], Whh[r3 * H + k0 + 1]) : 0ull;
            }
        }
    }
    float creg = 0.0f;

    __syncthreads();

    int buf = 0;

    // ---------------- phase 1: sequential pass with xg prefetch ----------------
    float xgA = ldx ? g_xg[rA] : 0.0f;   // t = 0
    float xgB = ldx ? g_xg[rB] : 0.0f;
#pragma unroll 1
    for (int t = 0; t < S; t++) {
        float xgA_n = 0.0f, xgB_n = 0.0f;
        if (ldx && t + 1 < S) {
            xgA_n = g_xg[(t + 1) * G4 + rA];
            xgB_n = g_xg[(t + 1) * G4 + rB];
        }
        LSTM_STEP(xgA, xgB)
        xgA = xgA_n;
        xgB = xgB_n;
    }

    // ---------------- phase 2: data-dependent scan ----------------
    float o0 = 0.0f, o1 = 0.0f;
    int consec = 0;

    int t = S / 2;
    xgA = ldx ? g_xg[t * G4 + rA] : 0.0f;
    xgB = ldx ? g_xg[t * G4 + rB] : 0.0f;

#pragma unroll 1
    for (int it = 0; it < ITERLIM; it++) {
        const int tp = (t + 1) & (S - 1);
        const int tm = (t - 1) & (S - 1);
        float pAx = 0, pBx = 0, mAx = 0, mBx = 0;
        if (ldx) {
            pAx = g_xg[tp * G4 + rA];
            pBx = g_xg[tp * G4 + rB];
            mAx = g_xg[tm * G4 + rA];
            mBx = g_xg[tm * G4 + rB];
        }

        LSTM_STEP(xgA, xgB)
        // new h is in hsf[buf]

        if (tid < 32) {
            const float* hv = &hsf[buf * HSTRIDE];
            float q0 = 0.0f, q1 = 0.0f, q2 = 0.0f;
            for (int k = tid; k < H; k += 32) {
                float h = hv[k];
                q0 += swfc[k] * h;
                q1 += swfc[H + k] * h;
                q2 += swfc[2 * H + k] * h;
            }
#pragma unroll
            for (int off = 16; off; off >>= 1) {
                q0 += __shfl_down_sync(0xffffffffu, q0, off);
                q1 += __shfl_down_sync(0xffffffffu, q1, off);
                q2 += __shfl_down_sync(0xffffffffu, q2, off);
            }
            if (tid == 0) {
                q0 += sbfc[0]; q1 += sbfc[1]; q2 += sbfc[2];
                o0 = q0;
                o1 = q1;
                consec = (q1 > 0.0f) ? (consec + 1) : 0;
                if (consec > 3) s_done = 1;
                s_idx = (q2 > 0.0f) ? tp : tm;
            }
        }
        __syncthreads();
        if (s_done) break;
        const int tn = s_idx;
        const bool fwd = (tn == tp);
        xgA = fwd ? pAx : mAx;
        xgB = fwd ? pBx : mBx;
        t = tn;
    }

    if (tid == 0) {
        out[0] = o0;
        out[1] = o1;
    }
}

// =====================================================================
// launch
// =====================================================================
extern "C" void kernel_launch(void* const* d_in, const int* in_sizes, int n_in,
                              void* d_out, int out_size) {
    const float* x   = (const float*)d_in[0];
    const float* Wih = (const float*)d_in[1];
    const float* Whh = (const float*)d_in[2];
    const float* bih = (const float*)d_in[3];
    const float* bhh = (const float*)d_in[4];
    const float* Wfc = (const float*)d_in[5];
    const float* bfc = (const float*)d_in[6];
    float* out = (float*)d_out;

    dim3 grid(S / BM, (G4 + BN - 1) / BN);
    gemm_xgates<<<grid, 256>>>(x, Wih, bih, bhh);
    lstm_scan<<<1, 256>>>(Whh, Wfc, bfc, out);
}